// round 12
// baseline (speedup 1.0000x reference)
#include <cuda_runtime.h>
#include <math.h>

#define T_STEPS 4096
#define BATCH   128
#define IN_DIM  96
#define H_DIM   64
#define OUT_DIM 2

#define WIN     8
#define NWIN    (T_STEPS / WIN)     // 512
#define CHUNK   64
#define NCHUNK  (T_STEPS / CHUNK)   // 64

typedef unsigned long long ull;

// Scratch
__device__ ull   g_M[(size_t)T_STEPS * BATCH];           // spike masks
__device__ ulonglong2 g_S[NCHUNK * BATCH];               // per-chunk (syn_end, mem_end)
__device__ ulonglong2 g_Pref[NCHUNK * BATCH];            // per-chunk initial (S, M)
__device__ float2 g_tab[CHUNK];                          // (b^{j+1}, g_j)

// ---------- packed f32x2 helpers ----------
__device__ __forceinline__ void fma2(ull& d, ull a, ull b) {
    asm("fma.rn.f32x2 %0, %1, %2, %0;" : "+l"(d) : "l"(a), "l"(b));
}
__device__ __forceinline__ ull fma2g(ull a, ull b, ull c) {
    ull d;
    asm("fma.rn.f32x2 %0, %1, %2, %3;" : "=l"(d) : "l"(a), "l"(b), "l"(c));
    return d;
}
__device__ __forceinline__ ull add2(ull a, ull b) {
    ull d;
    asm("add.rn.f32x2 %0, %1, %2;" : "=l"(d) : "l"(a), "l"(b));
    return d;
}
__device__ __forceinline__ ull mul2(ull a, ull b) {
    ull d;
    asm("mul.rn.f32x2 %0, %1, %2;" : "=l"(d) : "l"(a), "l"(b));
    return d;
}
__device__ __forceinline__ ull pack2(float x, float y) {
    ull r;
    asm("mov.b64 %0, {%1, %2};" : "=l"(r) : "f"(x), "f"(y));
    return r;
}
__device__ __forceinline__ float lo32(ull v) { return __uint_as_float((unsigned)v); }
__device__ __forceinline__ float hi32(ull v) { return __uint_as_float((unsigned)(v >> 32)); }

__device__ __forceinline__ unsigned smem_u32(const void* p) {
    unsigned a;
    asm("{ .reg .u64 t; cvta.to.shared.u64 t, %1; cvt.u32.u64 %0, t; }" : "=r"(a) : "l"(p));
    return a;
}
__device__ __forceinline__ ull lds_u64(unsigned a) {
    ull v;
    asm("ld.shared.b64 %0, [%1];" : "=l"(v) : "r"(a));
    return v;
}

// ============================================================
// FUSED kernel: on-the-fly input GEMV producers + serial scan
// consumer in one CTA per batch. 9 warps = 288 threads:
//   wid 8        : consumer (serial scan, 6-bit-LUT recurrent dot)
//   wid 1,2,3,5,6,7 : compute producers (SMSP 1..3, two each)
//   wid 0,4      : x stagers + partial combiners (SMSP 0, light)
// Phase = 8 time steps, double-buffered smem ring for P values.
// ============================================================
__global__ __launch_bounds__(288, 1) void scan_fused(const float* __restrict__ x,
                                                     const float* __restrict__ Wh,
                                                     const float* __restrict__ V,
                                                     float a_h, float b_h,
                                                     float aomb, float omb, float inv1) {
    extern __shared__ __align__(16) char dsm[];   // 6-bit LUT (+ alignment pad)
    __shared__ float x_s[2][WIN][IN_DIM];         // staged x rows (double buffer)
    __shared__ float pa[WIN][192];                // per-(h,kthird) partials
    __shared__ float ring[2][WIN][H_DIM];         // final P values (double buffer)

    const int tid  = threadIdx.x;
    const int wid  = tid >> 5;
    const int lane = tid & 31;
    const int b    = blockIdx.x;

    const unsigned raw32 = smem_u32(dsm);
    const unsigned abase = (raw32 + 16383u) & ~16383u;   // 16KB-aligned LUT base
    char* ab = dsm + (abase - raw32);

    // ---- consumer builds the recurrent LUT ----
    if (wid == 8) {
        for (int p = 0; p < 12; p++) {
            char* bpp = ab + p * 16384 + lane * 8;
            *(float2*)bpp = make_float2(0.f, 0.f);
            int pm = (p < 6) ? p : p - 6;
#pragma unroll
            for (int i = 0; i < 6; i++) {
                int l = 6 * pm + i;
                float2 c = make_float2(0.f, 0.f);
                if (l < 32) {
                    int j = (p < 6) ? 2 * l : 2 * l + 1;
                    c.x = V[(size_t)(2 * lane) * H_DIM + j];
                    c.y = V[(size_t)(2 * lane + 1) * H_DIM + j];
                }
                *(float2*)(bpp + (1u << i) * 256) = c;
            }
            for (int v = 3; v < 64; v++) {
                if ((v & (v - 1)) == 0) continue;
                float2 e1 = *(const float2*)(bpp + (v & (v - 1)) * 256);
                float2 e2 = *(const float2*)(bpp + (v & (-v)) * 256);
                *(float2*)(bpp + v * 256) = make_float2(e1.x + e2.x, e1.y + e2.y);
            }
        }
    }

    // ---- producer setup ----
    const bool is_comp = (wid == 1 || wid == 2 || wid == 3 || wid == 5 || wid == 6 || wid == 7);
    const bool is_comb = (wid == 0 || wid == 4);
    const bool is_stage = (tid < 192);
    const int sj = tid / 24, sq = tid % 24;

    int unit = 0, h_ = 0, kt = 0;
    ull Wreg[16];
    if (is_comp) {
        int cw = (wid < 4) ? (wid - 1) : (wid - 2);   // 0..5
        unit = cw * 32 + lane;                        // 0..191
        h_ = unit / 3;
        kt = unit - 3 * h_;
        const float* wr = Wh + (size_t)h_ * IN_DIM + kt * 32;
#pragma unroll
        for (int i = 0; i < 8; i++) {
            ulonglong2 wv = *(const ulonglong2*)(wr + 4 * i);
            Wreg[2 * i] = wv.x;
            Wreg[2 * i + 1] = wv.y;
        }
    }
    const int hc = lane + ((wid == 4) ? 32 : 0);      // combiner's h

    // pre-stage window 0 (rows -1..6)
    if (wid < 8 && is_stage) {
        int row = sj - 1;
        float4 f = make_float4(0.f, 0.f, 0.f, 0.f);
        if (row >= 0) f = *(const float4*)(x + ((size_t)row * BATCH + b) * IN_DIM + 4 * sq);
        *(float4*)&x_s[0][sj][4 * sq] = f;
    }

    // ---- consumer setup ----
    unsigned bp[12];
#pragma unroll
    for (int p = 0; p < 12; p++) bp[p] = abase + p * 16384 + lane * 8;
    const unsigned M6 = 0x3F00u;

    const ull a_h2  = pack2(a_h, a_h);
    const ull b_h2  = pack2(b_h, b_h);
    const ull omb2  = pack2(omb, omb);
    const ull aomb2 = pack2(aomb, aomb);
    const ull inv2  = pack2(inv1, inv1);
    const ull ninv2 = pack2(-inv1, -inv1);

    ull syn2 = 0ull, mem2 = 0ull;
    unsigned pm0 = 0u, pm1 = 0u;
    ull* mptr = g_M + b;

    // ================= phase loop =================
    for (int w = 0; w <= NWIN; w++) {
        __syncthreads();
        if (wid < 8) {
            if (w < NWIN) {
                // stage x for window w+1 (consumed next phase; LDG latency hidden)
                if (is_stage && (w + 1) < NWIN) {
                    int row = (w + 1) * WIN + sj - 1;
                    float4 f = *(const float4*)(x + ((size_t)row * BATCH + b) * IN_DIM + 4 * sq);
                    *(float4*)&x_s[(w + 1) & 1][sj][4 * sq] = f;
                }
                // compute partials for window w from x_s[w&1]
                if (is_comp) {
                    const float* xb = &x_s[w & 1][0][kt * 32];
#pragma unroll
                    for (int j = 0; j < WIN; j++) {
                        ull a0 = 0ull, a1 = 0ull;
#pragma unroll
                        for (int i = 0; i < 8; i++) {
                            ulonglong2 xv = *(const ulonglong2*)(xb + j * IN_DIM + 4 * i);
                            fma2(a0, xv.x, Wreg[2 * i]);
                            fma2(a1, xv.y, Wreg[2 * i + 1]);
                        }
                        ull s = add2(a0, a1);
                        pa[j][unit] = lo32(s) + hi32(s);
                    }
                }
                asm volatile("bar.sync 1, 256;" ::: "memory");
                // combine 3 partials -> ring[w&1]
                if (is_comb) {
#pragma unroll
                    for (int j = 0; j < WIN; j++)
                        ring[w & 1][j][hc] = pa[j][3 * hc] + pa[j][3 * hc + 1] + pa[j][3 * hc + 2];
                }
            }
        } else {
            if (w >= 1) {
                const int buf = (w - 1) & 1;
#pragma unroll
                for (int j = 0; j < WIN; j++) {
                    const int t = (w - 1) * WIN + j;

                    // base/threshold off the critical chain
                    ull base2 = fma2g(b_h2, mem2, mul2(aomb2, syn2));
                    ull th2   = fma2g(base2, ninv2, inv2);   // (1-base)/(1-b)

                    // 12 six-bit-group lookups (fixed cost)
                    ull h0 = lds_u64(((pm0 << 8)  & M6) | bp[0]);
                    ull h1 = lds_u64(((pm0 << 2)  & M6) | bp[1]);
                    ull h2 = lds_u64(((pm0 >> 4)  & M6) | bp[2]);
                    ull h3 = lds_u64(((pm0 >> 10) & M6) | bp[3]);
                    ull h4 = lds_u64(((pm0 >> 16) & M6) | bp[4]);
                    ull h5 = lds_u64(((pm0 >> 22) & M6) | bp[5]);
                    ull h6 = lds_u64(((pm1 << 8)  & M6) | bp[6]);
                    ull h7 = lds_u64(((pm1 << 2)  & M6) | bp[7]);
                    ull h8 = lds_u64(((pm1 >> 4)  & M6) | bp[8]);
                    ull h9 = lds_u64(((pm1 >> 10) & M6) | bp[9]);
                    ull hA = lds_u64(((pm1 >> 16) & M6) | bp[10]);
                    ull hB = lds_u64(((pm1 >> 22) & M6) | bp[11]);
                    ull cu = *(const ull*)&ring[buf][j][2 * lane];

                    ull t1 = add2(add2(h0, h1), add2(h2, h3));
                    ull t2 = add2(add2(h4, h5), add2(h6, h7));
                    ull t3 = add2(add2(h8, h9), add2(hA, hB));
                    ull tot = add2(add2(t1, t2), add2(t3, cu));

                    bool s0 = lo32(tot) > lo32(th2);
                    bool s1 = hi32(tot) > hi32(th2);
                    pm0 = __ballot_sync(0xffffffffu, s0);
                    pm1 = __ballot_sync(0xffffffffu, s1);

                    ull mem_pre = fma2g(omb2, tot, base2);
                    syn2 = fma2g(a_h2, syn2, tot);
                    mem2 = pack2(s0 ? 0.f : lo32(mem_pre),
                                 s1 ? 0.f : hi32(mem_pre));

                    if (lane == 0)
                        mptr[(size_t)t * BATCH] = (ull)pm0 | ((ull)pm1 << 32);
                }
            }
        }
    }
}

// ============================================================
// Readout (parallel-in-time linear recurrence), unchanged parts
// ============================================================
__global__ __launch_bounds__(128) void readout_chunks(const float* __restrict__ Wo,
                                                      float* __restrict__ out,
                                                      float a_o, float b_o) {
    __shared__ float2 lutOb[8 * 256];

    const int tid = threadIdx.x;
    const int c   = blockIdx.x;

    for (int idx = tid; idx < 8 * 256; idx += 128) {
        int pp = idx >> 8, v = idx & 255;
        float2 s = make_float2(0.f, 0.f);
#pragma unroll
        for (int i = 0; i < 8; i++) {
            if (v & (1 << i)) {
                int j = (pp < 4) ? 2 * (8 * pp + i) : 2 * (8 * (pp - 4) + i) + 1;
                s.x += Wo[j];
                s.y += Wo[H_DIM + j];
            }
        }
        lutOb[idx] = s;
    }
    __syncthreads();

    const int b = tid;
    const ull a_o2  = pack2(a_o, a_o);
    const ull b_o2  = pack2(b_o, b_o);
    const ull ombo2 = pack2(1.f - b_o, 1.f - b_o);

    ull syno2 = 0ull, memo2 = 0ull;

    const ull* mp = g_M + ((long long)c * CHUNK - 1) * BATCH + b;
    ull ring[8];
#pragma unroll
    for (int q = 0; q < 8; q++)
        ring[q] = (c == 0 && q == 0) ? 0ull : mp[(size_t)q * BATCH];
    const ull* pfm = mp + (size_t)8 * BATCH;

    ull* optr = (ull*)out + (size_t)c * CHUNK * BATCH + b;

    for (int jb = 0; jb < CHUNK; jb += 8) {
#pragma unroll
        for (int q8 = 0; q8 < 8; q8++) {
            const int j = jb + q8;
            ull m = ring[q8];
            if (j + 8 < CHUNK) ring[q8] = *pfm;
            pfm += BATCH;

            unsigned p0 = (unsigned)m, p1 = (unsigned)(m >> 32);
            ull r0 = add2(*(const ull*)&lutOb[0 * 256 + (p0 & 255u)],
                          *(const ull*)&lutOb[4 * 256 + (p1 & 255u)]);
            ull r1 = add2(*(const ull*)&lutOb[1 * 256 + ((p0 >> 8) & 255u)],
                          *(const ull*)&lutOb[5 * 256 + ((p1 >> 8) & 255u)]);
            ull r2 = add2(*(const ull*)&lutOb[2 * 256 + ((p0 >> 16) & 255u)],
                          *(const ull*)&lutOb[6 * 256 + ((p1 >> 16) & 255u)]);
            ull r3 = add2(*(const ull*)&lutOb[3 * 256 + (p0 >> 24)],
                          *(const ull*)&lutOb[7 * 256 + (p1 >> 24)]);
            ull d2 = add2(add2(r0, r1), add2(r2, r3));

            syno2 = fma2g(a_o2, syno2, d2);
            memo2 = fma2g(b_o2, memo2, mul2(ombo2, syno2));
            optr[(size_t)j * BATCH] = memo2;
        }
    }
    g_S[c * BATCH + b] = make_ulonglong2(syno2, memo2);
}

// chunk prefix with block-of-16 double-buffered prefetch
__global__ __launch_bounds__(128) void readout_prefix(float a_o, float b_o) {
    const int b = threadIdx.x;

    float ap = a_o, bpw = b_o, g = (1.f - b_o) * a_o;
    float a64 = 0.f, b64 = 0.f, g63 = 0.f;
    for (int j = 0; j < CHUNK; j++) {
        if (b == 0) g_tab[j] = make_float2(bpw, g);
        if (j == CHUNK - 1) { a64 = ap; b64 = bpw; g63 = g; }
        ap *= a_o;
        bpw *= b_o;
        g = b_o * g + (1.f - b_o) * ap;
    }

    const ull a64_2 = pack2(a64, a64);
    const ull b64_2 = pack2(b64, b64);
    const ull g63_2 = pack2(g63, g63);

    ulonglong2 buf[2][16];
#pragma unroll
    for (int q = 0; q < 16; q++) buf[0][q] = g_S[q * BATCH + b];

    ull S = 0ull, M = 0ull;
#pragma unroll
    for (int blk = 0; blk < 4; blk++) {
        if (blk < 3) {
#pragma unroll
            for (int q = 0; q < 16; q++)
                buf[(blk + 1) & 1][q] = g_S[((blk + 1) * 16 + q) * BATCH + b];
        }
#pragma unroll
        for (int q = 0; q < 16; q++) {
            int c = blk * 16 + q;
            g_Pref[c * BATCH + b] = make_ulonglong2(S, M);
            ulonglong2 sm = buf[blk & 1][q];
            ull Sold = S;
            S = fma2g(a64_2, S, sm.x);
            M = add2(fma2g(b64_2, M, sm.y), mul2(g63_2, Sold));
        }
    }
}

__global__ __launch_bounds__(256) void readout_fix(float* __restrict__ out) {
    const size_t idx = (size_t)blockIdx.x * 256 + threadIdx.x;  // t*BATCH + b
    const int t = (int)(idx >> 7);
    const int b = (int)(idx & 127);
    const int c = t >> 6;
    const int j = t & 63;

    float2 tab = g_tab[j];
    ulonglong2 pref = g_Pref[c * BATCH + b];
    ull fix = add2(mul2(pack2(tab.x, tab.x), pref.y),
                   mul2(pack2(tab.y, tab.y), pref.x));
    ull* o = (ull*)out + idx;
    *o = add2(*o, fix);
}

// ============================================================
extern "C" void kernel_launch(void* const* d_in, const int* in_sizes, int n_in,
                              void* d_out, int out_size) {
    const float* x  = (const float*)d_in[0];
    const float* Wh = (const float*)d_in[1];
    const float* V  = (const float*)d_in[2];
    const float* Wo = (const float*)d_in[3];
    float* out = (float*)d_out;

    const double S = log1p(exp(1.0));
    const float a_h = expf((float)(-0.004 / (S * 0.01)));
    const float b_h = expf((float)(-0.004 / (S * 0.02)));
    const float omb  = 1.f - b_h;
    const float aomb = a_h * omb;
    const float inv1 = 1.f / omb;

    const int smem_scan = 12 * 16384 + 16384;  // 208 KB dynamic (LUT + align pad)
    cudaFuncSetAttribute(scan_fused, cudaFuncAttributeMaxDynamicSharedMemorySize,
                         smem_scan);

    scan_fused<<<BATCH, 288, smem_scan>>>(x, Wh, V, a_h, b_h, aomb, omb, inv1);
    readout_chunks<<<NCHUNK, 128>>>(Wo, out, a_h, b_h);
    readout_prefix<<<1, 128>>>(a_h, b_h);
    readout_fix<<<(T_STEPS * BATCH) / 256, 256>>>(out);
}

// round 13
// speedup vs baseline: 1.5855x; 1.5855x over previous
#include <cuda_runtime.h>
#include <math.h>

#define T_STEPS 4096
#define BATCH   128
#define IN_DIM  96
#define H_DIM   64
#define OUT_DIM 2

#define CHUNK   64
#define NCHUNK  (T_STEPS / CHUNK)   // 64

typedef unsigned long long ull;

// Scratch (padded by 8 timesteps so prefetches need no bounds branch)
__device__ float g_P[(size_t)(T_STEPS + 8) * BATCH * H_DIM];
__device__ ull   g_M[(size_t)(T_STEPS + 8) * BATCH];
__device__ ulonglong2 g_S[NCHUNK * BATCH];
__device__ ulonglong2 g_Pref[NCHUNK * BATCH];
__device__ float2 g_tab[CHUNK];

// ---------- packed f32x2 helpers ----------
__device__ __forceinline__ void fma2(ull& d, ull a, ull b) {
    asm("fma.rn.f32x2 %0, %1, %2, %0;" : "+l"(d) : "l"(a), "l"(b));
}
__device__ __forceinline__ ull fma2g(ull a, ull b, ull c) {
    ull d;
    asm("fma.rn.f32x2 %0, %1, %2, %3;" : "=l"(d) : "l"(a), "l"(b), "l"(c));
    return d;
}
__device__ __forceinline__ ull add2(ull a, ull b) {
    ull d;
    asm("add.rn.f32x2 %0, %1, %2;" : "=l"(d) : "l"(a), "l"(b));
    return d;
}
__device__ __forceinline__ ull mul2(ull a, ull b) {
    ull d;
    asm("mul.rn.f32x2 %0, %1, %2;" : "=l"(d) : "l"(a), "l"(b));
    return d;
}
__device__ __forceinline__ ull pack2(float x, float y) {
    ull r;
    asm("mov.b64 %0, {%1, %2};" : "=l"(r) : "f"(x), "f"(y));
    return r;
}
__device__ __forceinline__ float lo32(ull v) { return __uint_as_float((unsigned)v); }
__device__ __forceinline__ float hi32(ull v) { return __uint_as_float((unsigned)(v >> 32)); }

__device__ __forceinline__ unsigned smem_u32(const void* p) {
    unsigned a;
    asm("{ .reg .u64 t; cvta.to.shared.u64 t, %1; cvt.u32.u64 %0, t; }" : "=r"(a) : "l"(p));
    return a;
}
__device__ __forceinline__ ull lds_u64(unsigned a) {
    ull v;
    asm("ld.shared.b64 %0, [%1];" : "=l"(v) : "r"(a));
    return v;
}
// branch-free predicated global store (avoids BSSY/BSYNC per step)
__device__ __forceinline__ void stg_pred(unsigned cond, ull* addr, ull v) {
    asm volatile(
        "{\n\t.reg .pred p;\n\tsetp.ne.u32 p, %0, 0;\n\t@p st.global.b64 [%1], %2;\n\t}"
        :: "r"(cond), "l"(addr), "l"(v) : "memory");
}

// ============================================================
// Kernel 1: P[g] = (g >= BATCH) ? x[g-BATCH,:] @ W_h.T : 0
// CTA tile 64 rows x 64 cols, 64 threads, thread tile 8x8.
// ============================================================
__global__ __launch_bounds__(64) void precompute_inp(const float* __restrict__ x,
                                                     const float* __restrict__ Wh) {
    __shared__ ull xp[48][64];
    __shared__ ull wp[48][64];

    const int tid = threadIdx.x;
    const long long row0 = (long long)blockIdx.x * 64;

    const int fr = tid >> 3;
    const int fq = tid & 7;

#pragma unroll
    for (int rr = 0; rr < 8; rr++) {
        int c = rr * 8 + fr;
        const float4* src = (const float4*)(Wh + (size_t)c * IN_DIM) + fq * 3;
#pragma unroll
        for (int j = 0; j < 3; j++) {
            float4 f = src[j];
            int kk = (fq * 3 + j) * 2;
            *(float2*)&wp[kk][c]     = make_float2(f.x, f.y);
            *(float2*)&wp[kk + 1][c] = make_float2(f.z, f.w);
        }
    }
#pragma unroll
    for (int rr = 0; rr < 8; rr++) {
        int r = rr * 8 + fr;
        long long g = row0 + r;
#pragma unroll
        for (int j = 0; j < 3; j++) {
            float4 f = make_float4(0.f, 0.f, 0.f, 0.f);
            if (g >= BATCH)
                f = ((const float4*)(x + (g - BATCH) * IN_DIM))[fq * 3 + j];
            int kk = (fq * 3 + j) * 2;
            *(float2*)&xp[kk][r]     = make_float2(f.x, f.y);
            *(float2*)&xp[kk + 1][r] = make_float2(f.z, f.w);
        }
    }
    __syncthreads();

    const int r0 = (tid & 7) * 8;
    const int c0 = (tid >> 3) * 8;

    ull acc[8][8];
#pragma unroll
    for (int i = 0; i < 8; i++)
#pragma unroll
        for (int j = 0; j < 8; j++) acc[i][j] = 0ull;

#pragma unroll 2
    for (int kk = 0; kk < 48; kk++) {
        ulonglong2 A[4], B[4];
#pragma unroll
        for (int j = 0; j < 4; j++) {
            A[j] = *(const ulonglong2*)&xp[kk][r0 + 2 * j];
            B[j] = *(const ulonglong2*)&wp[kk][c0 + 2 * j];
        }
#pragma unroll
        for (int ri = 0; ri < 8; ri++) {
            ull av = (ri & 1) ? A[ri >> 1].y : A[ri >> 1].x;
#pragma unroll
            for (int cj = 0; cj < 4; cj++) {
                fma2(acc[ri][2 * cj],     av, B[cj].x);
                fma2(acc[ri][2 * cj + 1], av, B[cj].y);
            }
        }
    }

#pragma unroll
    for (int ri = 0; ri < 8; ri++) {
        float4 o0, o1;
        o0.x = lo32(acc[ri][0]) + hi32(acc[ri][0]);
        o0.y = lo32(acc[ri][1]) + hi32(acc[ri][1]);
        o0.z = lo32(acc[ri][2]) + hi32(acc[ri][2]);
        o0.w = lo32(acc[ri][3]) + hi32(acc[ri][3]);
        o1.x = lo32(acc[ri][4]) + hi32(acc[ri][4]);
        o1.y = lo32(acc[ri][5]) + hi32(acc[ri][5]);
        o1.z = lo32(acc[ri][6]) + hi32(acc[ri][6]);
        o1.w = lo32(acc[ri][7]) + hi32(acc[ri][7]);
        float* dst = g_P + (size_t)(row0 + r0 + ri) * H_DIM + c0;
        *(float4*)dst       = o0;
        *(float4*)(dst + 4) = o1;
    }
}

// ============================================================
// Kernel 2: hidden scan, one warp per batch, 6-bit-group LUT,
// EXACT reference arithmetic for the spike decision.
// Branch-free inner loop: unconditional ring prefetch (padded
// g_P) + predicated mask store.
// ============================================================
__global__ __launch_bounds__(32, 1) void scan_kernel(const float* __restrict__ V,
                                                     float a_h, float b_h) {
    extern __shared__ __align__(16) char smem[];

    const int lane = threadIdx.x;
    const int b    = blockIdx.x;

    const unsigned raw32  = smem_u32(smem);
    const unsigned abase  = (raw32 + 16383u) & ~16383u;   // 16KB-aligned
    char* ab = smem + (abase - raw32);

    // ---- build LUT ----
    for (int p = 0; p < 12; p++) {
        char* bpp = ab + p * 16384 + lane * 8;
        *(float2*)bpp = make_float2(0.f, 0.f);
        int pm = (p < 6) ? p : p - 6;
#pragma unroll
        for (int i = 0; i < 6; i++) {
            int l = 6 * pm + i;
            float2 c = make_float2(0.f, 0.f);
            if (l < 32) {
                int j = (p < 6) ? 2 * l : 2 * l + 1;
                c.x = V[(size_t)(2 * lane) * H_DIM + j];
                c.y = V[(size_t)(2 * lane + 1) * H_DIM + j];
            }
            *(float2*)(bpp + (1u << i) * 256) = c;
        }
        for (int v = 3; v < 64; v++) {
            if ((v & (v - 1)) == 0) continue;
            float2 e1 = *(const float2*)(bpp + (v & (v - 1)) * 256);
            float2 e2 = *(const float2*)(bpp + (v & (-v)) * 256);
            *(float2*)(bpp + v * 256) = make_float2(e1.x + e2.x, e1.y + e2.y);
        }
    }
    __syncwarp();

    unsigned bp[12];
#pragma unroll
    for (int p = 0; p < 12; p++) bp[p] = abase + p * 16384 + lane * 8;

    const float omb_h = 1.f - b_h;
    const ull a_h2 = pack2(a_h, a_h);
    const ull omb2 = pack2(omb_h, omb_h);
    const ull b_h2 = pack2(b_h, b_h);

    ull syn2 = 0ull, mem2 = 0ull;

    const int strideP = BATCH * H_DIM;
    const float* p = g_P + (size_t)b * H_DIM + 2 * lane;
    float2 cur[8];
#pragma unroll
    for (int q = 0; q < 8; q++) cur[q] = *(const float2*)(p + (size_t)q * strideP);
    const float* pf = p + (size_t)8 * strideP;

    ull* mptr = g_M + b;
    unsigned pm0 = 0u, pm1 = 0u;
    const unsigned M6 = 0x3F00u;
    const unsigned is0 = (lane == 0) ? 1u : 0u;

    for (int tb = 0; tb < T_STEPS; tb += 8) {
#pragma unroll
        for (int q8 = 0; q8 < 8; q8++) {
            ull h0 = lds_u64(((pm0 << 8)  & M6) | bp[0]);
            ull h1 = lds_u64(((pm0 << 2)  & M6) | bp[1]);
            ull h2 = lds_u64(((pm0 >> 4)  & M6) | bp[2]);
            ull h3 = lds_u64(((pm0 >> 10) & M6) | bp[3]);
            ull h4 = lds_u64(((pm0 >> 16) & M6) | bp[4]);
            ull h5 = lds_u64(((pm0 >> 22) & M6) | bp[5]);
            ull h6 = lds_u64(((pm1 << 8)  & M6) | bp[6]);
            ull h7 = lds_u64(((pm1 << 2)  & M6) | bp[7]);
            ull h8 = lds_u64(((pm1 >> 4)  & M6) | bp[8]);
            ull h9 = lds_u64(((pm1 >> 10) & M6) | bp[9]);
            ull hA = lds_u64(((pm1 >> 16) & M6) | bp[10]);
            ull hB = lds_u64(((pm1 >> 22) & M6) | bp[11]);

            float2 c = cur[q8];
            cur[q8] = *(const float2*)pf;   // unconditional (g_P padded)
            pf += strideP;

            ull s01 = add2(h0, h1);
            ull s23 = add2(h2, h3);
            ull s45 = add2(h4, h5);
            ull s67 = add2(h6, h7);
            ull s89 = add2(h8, h9);
            ull sAB = add2(hA, hB);
            ull sA4 = add2(s01, s23);
            ull sB4 = add2(s45, s67);
            ull sC4 = add2(s89, sAB);
            ull sD4 = add2(pack2(c.x, c.y), sA4);
            ull tot = add2(add2(sB4, sC4), sD4);

            syn2 = fma2g(a_h2, syn2, tot);
            mem2 = fma2g(b_h2, mem2, mul2(omb2, syn2));
            float m0 = lo32(mem2), m1 = hi32(mem2);
            bool s0 = (m0 > 1.f);
            bool s1 = (m1 > 1.f);
            m0 = s0 ? 0.f : m0;
            m1 = s1 ? 0.f : m1;
            mem2 = pack2(m0, m1);
            pm0 = __ballot_sync(0xffffffffu, s0);
            pm1 = __ballot_sync(0xffffffffu, s1);

            stg_pred(is0, mptr, (ull)pm0 | ((ull)pm1 << 32));  // branch-free
            mptr += BATCH;
        }
    }
}

// ============================================================
// Kernel 3: per-chunk local readout scans (branch-free prefetch).
// ============================================================
__global__ __launch_bounds__(128) void readout_chunks(const float* __restrict__ Wo,
                                                      float* __restrict__ out,
                                                      float a_o, float b_o) {
    __shared__ float2 lutOb[8 * 256];

    const int tid = threadIdx.x;
    const int c   = blockIdx.x;

    for (int idx = tid; idx < 8 * 256; idx += 128) {
        int pp = idx >> 8, v = idx & 255;
        float2 s = make_float2(0.f, 0.f);
#pragma unroll
        for (int i = 0; i < 8; i++) {
            if (v & (1 << i)) {
                int j = (pp < 4) ? 2 * (8 * pp + i) : 2 * (8 * (pp - 4) + i) + 1;
                s.x += Wo[j];
                s.y += Wo[H_DIM + j];
            }
        }
        lutOb[idx] = s;
    }
    __syncthreads();

    const int b = tid;
    const ull a_o2  = pack2(a_o, a_o);
    const ull b_o2  = pack2(b_o, b_o);
    const ull ombo2 = pack2(1.f - b_o, 1.f - b_o);

    ull syno2 = 0ull, memo2 = 0ull;

    const ull* mp = g_M + ((long long)c * CHUNK - 1) * BATCH + b;
    ull ring[8];
#pragma unroll
    for (int q = 0; q < 8; q++)
        ring[q] = (c == 0 && q == 0) ? 0ull : mp[(size_t)q * BATCH];
    const ull* pfm = mp + (size_t)8 * BATCH;

    ull* optr = (ull*)out + (size_t)c * CHUNK * BATCH + b;

    for (int jb = 0; jb < CHUNK; jb += 8) {
#pragma unroll
        for (int q8 = 0; q8 < 8; q8++) {
            const int j = jb + q8;
            ull m = ring[q8];
            ring[q8] = *pfm;   // unconditional (g_M padded)
            pfm += BATCH;

            unsigned p0 = (unsigned)m, p1 = (unsigned)(m >> 32);
            ull r0 = add2(*(const ull*)&lutOb[0 * 256 + (p0 & 255u)],
                          *(const ull*)&lutOb[4 * 256 + (p1 & 255u)]);
            ull r1 = add2(*(const ull*)&lutOb[1 * 256 + ((p0 >> 8) & 255u)],
                          *(const ull*)&lutOb[5 * 256 + ((p1 >> 8) & 255u)]);
            ull r2 = add2(*(const ull*)&lutOb[2 * 256 + ((p0 >> 16) & 255u)],
                          *(const ull*)&lutOb[6 * 256 + ((p1 >> 16) & 255u)]);
            ull r3 = add2(*(const ull*)&lutOb[3 * 256 + (p0 >> 24)],
                          *(const ull*)&lutOb[7 * 256 + (p1 >> 24)]);
            ull d2 = add2(add2(r0, r1), add2(r2, r3));

            syno2 = fma2g(a_o2, syno2, d2);
            memo2 = fma2g(b_o2, memo2, mul2(ombo2, syno2));
            optr[(size_t)j * BATCH] = memo2;
        }
    }
    g_S[c * BATCH + b] = make_ulonglong2(syno2, memo2);
}

// ============================================================
// Kernel 4: chunk prefix (double-buffered block prefetch).
// ============================================================
__global__ __launch_bounds__(128) void readout_prefix(float a_o, float b_o) {
    const int b = threadIdx.x;

    float ap = a_o, bpw = b_o, g = (1.f - b_o) * a_o;
    float a64 = 0.f, b64 = 0.f, g63 = 0.f;
    for (int j = 0; j < CHUNK; j++) {
        if (b == 0) g_tab[j] = make_float2(bpw, g);
        if (j == CHUNK - 1) { a64 = ap; b64 = bpw; g63 = g; }
        ap *= a_o;
        bpw *= b_o;
        g = b_o * g + (1.f - b_o) * ap;
    }

    const ull a64_2 = pack2(a64, a64);
    const ull b64_2 = pack2(b64, b64);
    const ull g63_2 = pack2(g63, g63);

    ulonglong2 buf[2][16];
#pragma unroll
    for (int q = 0; q < 16; q++) buf[0][q] = g_S[q * BATCH + b];

    ull S = 0ull, M = 0ull;
#pragma unroll
    for (int blk = 0; blk < 4; blk++) {
        if (blk < 3) {
#pragma unroll
            for (int q = 0; q < 16; q++)
                buf[(blk + 1) & 1][q] = g_S[((blk + 1) * 16 + q) * BATCH + b];
        }
#pragma unroll
        for (int q = 0; q < 16; q++) {
            int c = blk * 16 + q;
            g_Pref[c * BATCH + b] = make_ulonglong2(S, M);
            ulonglong2 sm = buf[blk & 1][q];
            ull Sold = S;
            S = fma2g(a64_2, S, sm.x);
            M = add2(fma2g(b64_2, M, sm.y), mul2(g63_2, Sold));
        }
    }
}

// ============================================================
// Kernel 5: fixup: out[t][b] += b^{j+1}*M_c + g_j*S_c
// ============================================================
__global__ __launch_bounds__(256) void readout_fix(float* __restrict__ out) {
    const size_t idx = (size_t)blockIdx.x * 256 + threadIdx.x;
    const int t = (int)(idx >> 7);
    const int b = (int)(idx & 127);
    const int c = t >> 6;
    const int j = t & 63;

    float2 tab = g_tab[j];
    ulonglong2 pref = g_Pref[c * BATCH + b];
    ull fix = add2(mul2(pack2(tab.x, tab.x), pref.y),
                   mul2(pack2(tab.y, tab.y), pref.x));
    ull* o = (ull*)out + idx;
    *o = add2(*o, fix);
}

// ============================================================
extern "C" void kernel_launch(void* const* d_in, const int* in_sizes, int n_in,
                              void* d_out, int out_size) {
    const float* x  = (const float*)d_in[0];
    const float* Wh = (const float*)d_in[1];
    const float* V  = (const float*)d_in[2];
    const float* Wo = (const float*)d_in[3];
    float* out = (float*)d_out;

    const double S = log1p(exp(1.0));
    const float a_h = expf((float)(-0.004 / (S * 0.01)));
    const float b_h = expf((float)(-0.004 / (S * 0.02)));

    const int smem_scan = 12 * 16384 + 16384;  // 208 KB
    cudaFuncSetAttribute(scan_kernel, cudaFuncAttributeMaxDynamicSharedMemorySize,
                         smem_scan);

    precompute_inp<<<(T_STEPS * BATCH) / 64, 64>>>(x, Wh);
    scan_kernel<<<BATCH, 32, smem_scan>>>(V, a_h, b_h);
    readout_chunks<<<NCHUNK, 128>>>(Wo, out, a_h, b_h);
    readout_prefix<<<1, 128>>>(a_h, b_h);
    readout_fix<<<(T_STEPS * BATCH) / 256, 256>>>(out);
}

// round 14
// speedup vs baseline: 1.6402x; 1.0345x over previous
#include <cuda_runtime.h>
#include <math.h>

#define T_STEPS 4096
#define BATCH   128
#define IN_DIM  96
#define H_DIM   64
#define OUT_DIM 2

#define CHUNK   32
#define NCHUNK  (T_STEPS / CHUNK)   // 128

typedef unsigned long long ull;

// Scratch (padded by 8 timesteps so prefetches need no bounds branch)
__device__ float g_P[(size_t)(T_STEPS + 8) * BATCH * H_DIM];
__device__ ull   g_M[(size_t)(T_STEPS + 8) * BATCH];
__device__ ulonglong2 g_S[NCHUNK * BATCH];
__device__ ulonglong2 g_Pref[NCHUNK * BATCH];
__device__ float2 g_tab[CHUNK];

// ---------- packed f32x2 helpers ----------
__device__ __forceinline__ void fma2(ull& d, ull a, ull b) {
    asm("fma.rn.f32x2 %0, %1, %2, %0;" : "+l"(d) : "l"(a), "l"(b));
}
__device__ __forceinline__ ull fma2g(ull a, ull b, ull c) {
    ull d;
    asm("fma.rn.f32x2 %0, %1, %2, %3;" : "=l"(d) : "l"(a), "l"(b), "l"(c));
    return d;
}
__device__ __forceinline__ ull add2(ull a, ull b) {
    ull d;
    asm("add.rn.f32x2 %0, %1, %2;" : "=l"(d) : "l"(a), "l"(b));
    return d;
}
__device__ __forceinline__ ull mul2(ull a, ull b) {
    ull d;
    asm("mul.rn.f32x2 %0, %1, %2;" : "=l"(d) : "l"(a), "l"(b));
    return d;
}
__device__ __forceinline__ ull pack2(float x, float y) {
    ull r;
    asm("mov.b64 %0, {%1, %2};" : "=l"(r) : "f"(x), "f"(y));
    return r;
}
__device__ __forceinline__ float lo32(ull v) { return __uint_as_float((unsigned)v); }
__device__ __forceinline__ float hi32(ull v) { return __uint_as_float((unsigned)(v >> 32)); }

__device__ __forceinline__ unsigned smem_u32(const void* p) {
    unsigned a;
    asm("{ .reg .u64 t; cvta.to.shared.u64 t, %1; cvt.u32.u64 %0, t; }" : "=r"(a) : "l"(p));
    return a;
}
__device__ __forceinline__ ull lds_u64(unsigned a) {
    ull v;
    asm("ld.shared.b64 %0, [%1];" : "=l"(v) : "r"(a));
    return v;
}
__device__ __forceinline__ void stg_pred(unsigned cond, ull* addr, ull v) {
    asm volatile(
        "{\n\t.reg .pred p;\n\tsetp.ne.u32 p, %0, 0;\n\t@p st.global.b64 [%1], %2;\n\t}"
        :: "r"(cond), "l"(addr), "l"(v) : "memory");
}

// ============================================================
// Kernel 1: P[g] = (g >= BATCH) ? x[g-BATCH,:] @ W_h.T : 0
// ============================================================
__global__ __launch_bounds__(64) void precompute_inp(const float* __restrict__ x,
                                                     const float* __restrict__ Wh) {
    __shared__ ull xp[48][64];
    __shared__ ull wp[48][64];

    const int tid = threadIdx.x;
    const long long row0 = (long long)blockIdx.x * 64;

    const int fr = tid >> 3;
    const int fq = tid & 7;

#pragma unroll
    for (int rr = 0; rr < 8; rr++) {
        int c = rr * 8 + fr;
        const float4* src = (const float4*)(Wh + (size_t)c * IN_DIM) + fq * 3;
#pragma unroll
        for (int j = 0; j < 3; j++) {
            float4 f = src[j];
            int kk = (fq * 3 + j) * 2;
            *(float2*)&wp[kk][c]     = make_float2(f.x, f.y);
            *(float2*)&wp[kk + 1][c] = make_float2(f.z, f.w);
        }
    }
#pragma unroll
    for (int rr = 0; rr < 8; rr++) {
        int r = rr * 8 + fr;
        long long g = row0 + r;
#pragma unroll
        for (int j = 0; j < 3; j++) {
            float4 f = make_float4(0.f, 0.f, 0.f, 0.f);
            if (g >= BATCH)
                f = ((const float4*)(x + (g - BATCH) * IN_DIM))[fq * 3 + j];
            int kk = (fq * 3 + j) * 2;
            *(float2*)&xp[kk][r]     = make_float2(f.x, f.y);
            *(float2*)&xp[kk + 1][r] = make_float2(f.z, f.w);
        }
    }
    __syncthreads();

    const int r0 = (tid & 7) * 8;
    const int c0 = (tid >> 3) * 8;

    ull acc[8][8];
#pragma unroll
    for (int i = 0; i < 8; i++)
#pragma unroll
        for (int j = 0; j < 8; j++) acc[i][j] = 0ull;

#pragma unroll 2
    for (int kk = 0; kk < 48; kk++) {
        ulonglong2 A[4], B[4];
#pragma unroll
        for (int j = 0; j < 4; j++) {
            A[j] = *(const ulonglong2*)&xp[kk][r0 + 2 * j];
            B[j] = *(const ulonglong2*)&wp[kk][c0 + 2 * j];
        }
#pragma unroll
        for (int ri = 0; ri < 8; ri++) {
            ull av = (ri & 1) ? A[ri >> 1].y : A[ri >> 1].x;
#pragma unroll
            for (int cj = 0; cj < 4; cj++) {
                fma2(acc[ri][2 * cj],     av, B[cj].x);
                fma2(acc[ri][2 * cj + 1], av, B[cj].y);
            }
        }
    }

#pragma unroll
    for (int ri = 0; ri < 8; ri++) {
        float4 o0, o1;
        o0.x = lo32(acc[ri][0]) + hi32(acc[ri][0]);
        o0.y = lo32(acc[ri][1]) + hi32(acc[ri][1]);
        o0.z = lo32(acc[ri][2]) + hi32(acc[ri][2]);
        o0.w = lo32(acc[ri][3]) + hi32(acc[ri][3]);
        o1.x = lo32(acc[ri][4]) + hi32(acc[ri][4]);
        o1.y = lo32(acc[ri][5]) + hi32(acc[ri][5]);
        o1.z = lo32(acc[ri][6]) + hi32(acc[ri][6]);
        o1.w = lo32(acc[ri][7]) + hi32(acc[ri][7]);
        float* dst = g_P + (size_t)(row0 + r0 + ri) * H_DIM + c0;
        *(float4*)dst       = o0;
        *(float4*)(dst + 4) = o1;
    }
}

// ============================================================
// Kernel 2: hidden scan, one warp per batch, ELEVEN 6-bit groups
// over the combined 64-bit mask m = (pm1:pm0):
//   bit n (n<32)  = spike of neuron 2n      (pm0)
//   bit n (n>=32) = spike of neuron 2(n-32)+1 (pm1)
// Group q covers bits 6q..6q+5 (q=10: 4 bits). Lookup address
// = bp[q] | field<<8 (disjoint bits: 1 shift + 1 LOP3 each).
// ============================================================
__global__ __launch_bounds__(32, 1) void scan_kernel(const float* __restrict__ V,
                                                     float a_h, float b_h) {
    extern __shared__ __align__(16) char smem[];

    const int lane = threadIdx.x;
    const int b    = blockIdx.x;

    const unsigned raw32  = smem_u32(smem);
    const unsigned abase  = (raw32 + 16383u) & ~16383u;   // 16KB-aligned
    char* ab = smem + (abase - raw32);

    // ---- build LUT: 11 positions x 64 entries x 32 lanes x float2 ----
    for (int p = 0; p < 11; p++) {
        char* bpp = ab + p * 16384 + lane * 8;
        *(float2*)bpp = make_float2(0.f, 0.f);
#pragma unroll
        for (int i = 0; i < 6; i++) {
            int n = 6 * p + i;
            float2 c = make_float2(0.f, 0.f);
            if (n < 64) {
                int j = (n < 32) ? 2 * n : 2 * (n - 32) + 1;
                c.x = V[(size_t)(2 * lane) * H_DIM + j];
                c.y = V[(size_t)(2 * lane + 1) * H_DIM + j];
            }
            *(float2*)(bpp + (1u << i) * 256) = c;
        }
        for (int v = 3; v < 64; v++) {
            if ((v & (v - 1)) == 0) continue;
            float2 e1 = *(const float2*)(bpp + (v & (v - 1)) * 256);
            float2 e2 = *(const float2*)(bpp + (v & (-v)) * 256);
            *(float2*)(bpp + v * 256) = make_float2(e1.x + e2.x, e1.y + e2.y);
        }
    }
    __syncwarp();

    unsigned bp[11];
#pragma unroll
    for (int p = 0; p < 11; p++) bp[p] = abase + p * 16384 + lane * 8;

    const float omb_h = 1.f - b_h;
    const ull a_h2 = pack2(a_h, a_h);
    const ull omb2 = pack2(omb_h, omb_h);
    const ull b_h2 = pack2(b_h, b_h);

    ull syn2 = 0ull, mem2 = 0ull;

    const int strideP = BATCH * H_DIM;
    const float* p = g_P + (size_t)b * H_DIM + 2 * lane;
    float2 cur[8];
#pragma unroll
    for (int q = 0; q < 8; q++) cur[q] = *(const float2*)(p + (size_t)q * strideP);
    const float* pf = p + (size_t)8 * strideP;

    ull* mptr = g_M + b;
    unsigned pm0 = 0u, pm1 = 0u;
    const unsigned M6 = 0x3F00u;
    const unsigned is0 = (lane == 0) ? 1u : 0u;

    for (int tb = 0; tb < T_STEPS; tb += 8) {
#pragma unroll
        for (int q8 = 0; q8 < 8; q8++) {
            // 11 lookups: fields at bits 6q of (pm1:pm0), placed at addr bits 8..13
            ull h0 = lds_u64(((pm0 << 8)  & M6) | bp[0]);
            ull h1 = lds_u64(((pm0 << 2)  & M6) | bp[1]);
            ull h2 = lds_u64(((pm0 >> 4)  & M6) | bp[2]);
            ull h3 = lds_u64(((pm0 >> 10) & M6) | bp[3]);
            ull h4 = lds_u64(((pm0 >> 16) & M6) | bp[4]);
            ull h5 = lds_u64((__funnelshift_r(pm0, pm1, 22) & M6) | bp[5]);
            ull h6 = lds_u64(((pm1 << 4)  & M6) | bp[6]);
            ull h7 = lds_u64(((pm1 >> 2)  & M6) | bp[7]);
            ull h8 = lds_u64(((pm1 >> 8)  & M6) | bp[8]);
            ull h9 = lds_u64(((pm1 >> 14) & M6) | bp[9]);
            ull hA = lds_u64(((pm1 >> 20) & M6) | bp[10]);

            float2 c = cur[q8];
            cur[q8] = *(const float2*)pf;   // unconditional (g_P padded)
            pf += strideP;

            ull s01 = add2(h0, h1);
            ull s23 = add2(h2, h3);
            ull s45 = add2(h4, h5);
            ull s67 = add2(h6, h7);
            ull s89 = add2(h8, h9);
            ull sAc = add2(hA, pack2(c.x, c.y));
            ull t1  = add2(s01, s23);
            ull t2  = add2(s45, s67);
            ull t3  = add2(s89, sAc);
            ull tot = add2(add2(t1, t2), t3);

            syn2 = fma2g(a_h2, syn2, tot);
            mem2 = fma2g(b_h2, mem2, mul2(omb2, syn2));
            float m0 = lo32(mem2), m1 = hi32(mem2);
            bool s0 = (m0 > 1.f);
            bool s1 = (m1 > 1.f);
            m0 = s0 ? 0.f : m0;
            m1 = s1 ? 0.f : m1;
            mem2 = pack2(m0, m1);
            pm0 = __ballot_sync(0xffffffffu, s0);
            pm1 = __ballot_sync(0xffffffffu, s1);

            stg_pred(is0, mptr, (ull)pm0 | ((ull)pm1 << 32));
            mptr += BATCH;
        }
    }
}

// ============================================================
// Kernel 3: per-chunk local readout scans (CHUNK=32, 128 CTAs).
// ============================================================
__global__ __launch_bounds__(128) void readout_chunks(const float* __restrict__ Wo,
                                                      float* __restrict__ out,
                                                      float a_o, float b_o) {
    __shared__ float2 lutOb[8 * 256];

    const int tid = threadIdx.x;
    const int c   = blockIdx.x;

    for (int idx = tid; idx < 8 * 256; idx += 128) {
        int pp = idx >> 8, v = idx & 255;
        float2 s = make_float2(0.f, 0.f);
#pragma unroll
        for (int i = 0; i < 8; i++) {
            if (v & (1 << i)) {
                int j = (pp < 4) ? 2 * (8 * pp + i) : 2 * (8 * (pp - 4) + i) + 1;
                s.x += Wo[j];
                s.y += Wo[H_DIM + j];
            }
        }
        lutOb[idx] = s;
    }
    __syncthreads();

    const int b = tid;
    const ull a_o2  = pack2(a_o, a_o);
    const ull b_o2  = pack2(b_o, b_o);
    const ull ombo2 = pack2(1.f - b_o, 1.f - b_o);

    ull syno2 = 0ull, memo2 = 0ull;

    const ull* mp = g_M + ((long long)c * CHUNK - 1) * BATCH + b;
    ull ring[8];
#pragma unroll
    for (int q = 0; q < 8; q++)
        ring[q] = (c == 0 && q == 0) ? 0ull : mp[(size_t)q * BATCH];
    const ull* pfm = mp + (size_t)8 * BATCH;

    ull* optr = (ull*)out + (size_t)c * CHUNK * BATCH + b;

    for (int jb = 0; jb < CHUNK; jb += 8) {
#pragma unroll
        for (int q8 = 0; q8 < 8; q8++) {
            const int j = jb + q8;
            ull m = ring[q8];
            ring[q8] = *pfm;   // unconditional (g_M padded)
            pfm += BATCH;

            unsigned p0 = (unsigned)m, p1 = (unsigned)(m >> 32);
            ull r0 = add2(*(const ull*)&lutOb[0 * 256 + (p0 & 255u)],
                          *(const ull*)&lutOb[4 * 256 + (p1 & 255u)]);
            ull r1 = add2(*(const ull*)&lutOb[1 * 256 + ((p0 >> 8) & 255u)],
                          *(const ull*)&lutOb[5 * 256 + ((p1 >> 8) & 255u)]);
            ull r2 = add2(*(const ull*)&lutOb[2 * 256 + ((p0 >> 16) & 255u)],
                          *(const ull*)&lutOb[6 * 256 + ((p1 >> 16) & 255u)]);
            ull r3 = add2(*(const ull*)&lutOb[3 * 256 + (p0 >> 24)],
                          *(const ull*)&lutOb[7 * 256 + (p1 >> 24)]);
            ull d2 = add2(add2(r0, r1), add2(r2, r3));

            syno2 = fma2g(a_o2, syno2, d2);
            memo2 = fma2g(b_o2, memo2, mul2(ombo2, syno2));
            optr[(size_t)j * BATCH] = memo2;
        }
    }
    g_S[c * BATCH + b] = make_ulonglong2(syno2, memo2);
}

// ============================================================
// Kernel 4: chunk prefix (NCHUNK=128, 16-deep block prefetch).
// ============================================================
__global__ __launch_bounds__(128) void readout_prefix(float a_o, float b_o) {
    const int b = threadIdx.x;

    float ap = a_o, bpw = b_o, g = (1.f - b_o) * a_o;
    float aC = 0.f, bC = 0.f, gC = 0.f;
    for (int j = 0; j < CHUNK; j++) {
        if (b == 0) g_tab[j] = make_float2(bpw, g);
        if (j == CHUNK - 1) { aC = ap; bC = bpw; gC = g; }
        ap *= a_o;
        bpw *= b_o;
        g = b_o * g + (1.f - b_o) * ap;
    }

    const ull aC2 = pack2(aC, aC);
    const ull bC2 = pack2(bC, bC);
    const ull gC2 = pack2(gC, gC);

    ulonglong2 buf[2][16];
#pragma unroll
    for (int q = 0; q < 16; q++) buf[0][q] = g_S[q * BATCH + b];

    ull S = 0ull, M = 0ull;
#pragma unroll
    for (int blk = 0; blk < NCHUNK / 16; blk++) {
        if (blk < NCHUNK / 16 - 1) {
#pragma unroll
            for (int q = 0; q < 16; q++)
                buf[(blk + 1) & 1][q] = g_S[((blk + 1) * 16 + q) * BATCH + b];
        }
#pragma unroll
        for (int q = 0; q < 16; q++) {
            int c = blk * 16 + q;
            g_Pref[c * BATCH + b] = make_ulonglong2(S, M);
            ulonglong2 sm = buf[blk & 1][q];
            ull Sold = S;
            S = fma2g(aC2, S, sm.x);
            M = add2(fma2g(bC2, M, sm.y), mul2(gC2, Sold));
        }
    }
}

// ============================================================
// Kernel 5: fixup: out[t][b] += b^{j+1}*M_c + g_j*S_c
// ============================================================
__global__ __launch_bounds__(256) void readout_fix(float* __restrict__ out) {
    const size_t idx = (size_t)blockIdx.x * 256 + threadIdx.x;
    const int t = (int)(idx >> 7);
    const int b = (int)(idx & 127);
    const int c = t / CHUNK;
    const int j = t % CHUNK;

    float2 tab = g_tab[j];
    ulonglong2 pref = g_Pref[c * BATCH + b];
    ull fix = add2(mul2(pack2(tab.x, tab.x), pref.y),
                   mul2(pack2(tab.y, tab.y), pref.x));
    ull* o = (ull*)out + idx;
    *o = add2(*o, fix);
}

// ============================================================
extern "C" void kernel_launch(void* const* d_in, const int* in_sizes, int n_in,
                              void* d_out, int out_size) {
    const float* x  = (const float*)d_in[0];
    const float* Wh = (const float*)d_in[1];
    const float* V  = (const float*)d_in[2];
    const float* Wo = (const float*)d_in[3];
    float* out = (float*)d_out;

    const double S = log1p(exp(1.0));
    const float a_h = expf((float)(-0.004 / (S * 0.01)));
    const float b_h = expf((float)(-0.004 / (S * 0.02)));

    const int smem_scan = 11 * 16384 + 16384;  // 192 KB (incl. alignment pad)
    cudaFuncSetAttribute(scan_kernel, cudaFuncAttributeMaxDynamicSharedMemorySize,
                         smem_scan);

    precompute_inp<<<(T_STEPS * BATCH) / 64, 64>>>(x, Wh);
    scan_kernel<<<BATCH, 32, smem_scan>>>(V, a_h, b_h);
    readout_chunks<<<NCHUNK, 128>>>(Wo, out, a_h, b_h);
    readout_prefix<<<1, 128>>>(a_h, b_h);
    readout_fix<<<(T_STEPS * BATCH) / 256, 256>>>(out);
}

// round 15
// speedup vs baseline: 1.8994x; 1.1581x over previous
#include <cuda_runtime.h>
#include <math.h>

#define T_STEPS 4096
#define BATCH   128
#define IN_DIM  96
#define H_DIM   64
#define OUT_DIM 2

#define CHUNK   32
#define NCHUNK  (T_STEPS / CHUNK)   // 128 (readout chunking)

#define TCH     64                  // producer/scan sync chunk (timesteps)
#define NTCH    (T_STEPS / TCH)     // 64
#define PRE_CTAS  128
#define SCAN_CTAS 128

typedef unsigned long long ull;

// Scratch (padded by 8 timesteps so prefetches need no bounds branch)
__device__ float g_P[(size_t)(T_STEPS + 8) * BATCH * H_DIM];
__device__ ull   g_M[(size_t)(T_STEPS + 8) * BATCH];
__device__ ulonglong2 g_S[NCHUNK * BATCH];
__device__ ulonglong2 g_Pref[NCHUNK * BATCH];
__device__ float2 g_tab[CHUNK];
__device__ int    g_done[NTCH];     // producer progress counters

// ---------- packed f32x2 helpers ----------
__device__ __forceinline__ void fma2(ull& d, ull a, ull b) {
    asm("fma.rn.f32x2 %0, %1, %2, %0;" : "+l"(d) : "l"(a), "l"(b));
}
__device__ __forceinline__ ull fma2g(ull a, ull b, ull c) {
    ull d;
    asm("fma.rn.f32x2 %0, %1, %2, %3;" : "=l"(d) : "l"(a), "l"(b), "l"(c));
    return d;
}
__device__ __forceinline__ ull add2(ull a, ull b) {
    ull d;
    asm("add.rn.f32x2 %0, %1, %2;" : "=l"(d) : "l"(a), "l"(b));
    return d;
}
__device__ __forceinline__ ull mul2(ull a, ull b) {
    ull d;
    asm("mul.rn.f32x2 %0, %1, %2;" : "=l"(d) : "l"(a), "l"(b));
    return d;
}
__device__ __forceinline__ ull pack2(float x, float y) {
    ull r;
    asm("mov.b64 %0, {%1, %2};" : "=l"(r) : "f"(x), "f"(y));
    return r;
}
__device__ __forceinline__ float lo32(ull v) { return __uint_as_float((unsigned)v); }
__device__ __forceinline__ float hi32(ull v) { return __uint_as_float((unsigned)(v >> 32)); }

__device__ __forceinline__ unsigned smem_u32(const void* p) {
    unsigned a;
    asm("{ .reg .u64 t; cvta.to.shared.u64 t, %1; cvt.u32.u64 %0, t; }" : "=r"(a) : "l"(p));
    return a;
}
__device__ __forceinline__ ull lds_u64(unsigned a) {
    ull v;
    asm("ld.shared.b64 %0, [%1];" : "=l"(v) : "r"(a));
    return v;
}
__device__ __forceinline__ void stg_pred(unsigned cond, ull* addr, ull v) {
    asm volatile(
        "{\n\t.reg .pred p;\n\tsetp.ne.u32 p, %0, 0;\n\t@p st.global.b64 [%1], %2;\n\t}"
        :: "r"(cond), "l"(addr), "l"(v) : "memory");
}
__device__ __forceinline__ void release_inc(int* p) {
    asm volatile("red.release.gpu.global.add.s32 [%0], 1;" :: "l"(p) : "memory");
}
__device__ __forceinline__ int acquire_ld(const int* p) {
    int v;
    asm volatile("ld.acquire.gpu.global.s32 %0, [%1];" : "=r"(v) : "l"(p) : "memory");
    return v;
}

// ============================================================
// Kernel 0: reset producer progress counters (graph-replay safe)
// ============================================================
__global__ void zero_done() {
    if (threadIdx.x < NTCH) g_done[threadIdx.x] = 0;
}

// ============================================================
// FUSED kernel: 256 CTAs x 128 threads, 112KB dynamic smem.
//  bids 0..127   : producers (warps 0,1 active -> SMSP 0,1)
//    CTA p, chunk c: computes g_P rows [ (c*128+p)*64, +64 )
//    (= x[t-1] @ W_h.T with the one-step shift), then
//    __threadfence + red.release(g_done[c]).
//  bids 128..255 : scan CTAs (warp 3 active -> SMSP 3)
//    one warp per batch; 13x 5-bit-group LUT recurrent dot;
//    polls g_done[c+1] with ld.acquire once per 64 steps.
// Dynamic smem is aliased: producers use it as xp/wp tiles,
// scan CTAs as the 104KB LUT (8KB-aligned).
// ============================================================
__global__ __launch_bounds__(128, 1) void fused_kernel(const float* __restrict__ x,
                                                       const float* __restrict__ Wh,
                                                       const float* __restrict__ V,
                                                       float a_h, float b_h) {
    extern __shared__ __align__(16) char dsm[];
    const int tid  = threadIdx.x;
    const int bidx = blockIdx.x;

    if (bidx < PRE_CTAS) {
        // ================= PRODUCER =================
        if (tid >= 64) return;   // warps 0,1 only

        ull (*xp)[64] = (ull(*)[64])(dsm);            // 24 KB
        ull (*wp)[64] = (ull(*)[64])(dsm + 24576);    // 24 KB

        const int fr = tid >> 3;
        const int fq = tid & 7;

        // ---- W fill (once) ----
#pragma unroll
        for (int rr = 0; rr < 8; rr++) {
            int c = rr * 8 + fr;
            const float4* src = (const float4*)(Wh + (size_t)c * IN_DIM) + fq * 3;
#pragma unroll
            for (int j = 0; j < 3; j++) {
                float4 f = src[j];
                int kk = (fq * 3 + j) * 2;
                *(float2*)&wp[kk][c]     = make_float2(f.x, f.y);
                *(float2*)&wp[kk + 1][c] = make_float2(f.z, f.w);
            }
        }

        const int r0 = (tid & 7) * 8;
        const int c0 = (tid >> 3) * 8;

        for (int c = 0; c < NTCH; c++) {
            const long long row0 = ((long long)c * 128 + bidx) * 64;

            // ---- x fill (shifted by one step; t==0 rows zero) ----
#pragma unroll
            for (int rr = 0; rr < 8; rr++) {
                int r = rr * 8 + fr;
                long long g = row0 + r;
#pragma unroll
                for (int j = 0; j < 3; j++) {
                    float4 f = make_float4(0.f, 0.f, 0.f, 0.f);
                    if (g >= BATCH)
                        f = ((const float4*)(x + (g - BATCH) * IN_DIM))[fq * 3 + j];
                    int kk = (fq * 3 + j) * 2;
                    *(float2*)&xp[kk][r]     = make_float2(f.x, f.y);
                    *(float2*)&xp[kk + 1][r] = make_float2(f.z, f.w);
                }
            }
            __syncthreads();

            ull acc[8][8];
#pragma unroll
            for (int i = 0; i < 8; i++)
#pragma unroll
                for (int j = 0; j < 8; j++) acc[i][j] = 0ull;

#pragma unroll 2
            for (int kk = 0; kk < 48; kk++) {
                ulonglong2 A[4], B[4];
#pragma unroll
                for (int j = 0; j < 4; j++) {
                    A[j] = *(const ulonglong2*)&xp[kk][r0 + 2 * j];
                    B[j] = *(const ulonglong2*)&wp[kk][c0 + 2 * j];
                }
#pragma unroll
                for (int ri = 0; ri < 8; ri++) {
                    ull av = (ri & 1) ? A[ri >> 1].y : A[ri >> 1].x;
#pragma unroll
                    for (int cj = 0; cj < 4; cj++) {
                        fma2(acc[ri][2 * cj],     av, B[cj].x);
                        fma2(acc[ri][2 * cj + 1], av, B[cj].y);
                    }
                }
            }

#pragma unroll
            for (int ri = 0; ri < 8; ri++) {
                float4 o0, o1;
                o0.x = lo32(acc[ri][0]) + hi32(acc[ri][0]);
                o0.y = lo32(acc[ri][1]) + hi32(acc[ri][1]);
                o0.z = lo32(acc[ri][2]) + hi32(acc[ri][2]);
                o0.w = lo32(acc[ri][3]) + hi32(acc[ri][3]);
                o1.x = lo32(acc[ri][4]) + hi32(acc[ri][4]);
                o1.y = lo32(acc[ri][5]) + hi32(acc[ri][5]);
                o1.z = lo32(acc[ri][6]) + hi32(acc[ri][6]);
                o1.w = lo32(acc[ri][7]) + hi32(acc[ri][7]);
                float* dst = g_P + (size_t)(row0 + r0 + ri) * H_DIM + c0;
                *(float4*)dst       = o0;
                *(float4*)(dst + 4) = o1;
            }

            __threadfence();      // publish g_P writes at gpu scope
            __syncthreads();      // all threads' stores+fences done
            if (tid == 0) release_inc(&g_done[c]);
        }
        return;
    }

    // ================= SCAN =================
    if (tid < 96) return;         // warp 3 only (SMSP3)
    const int lane = tid - 96;
    const int b    = bidx - PRE_CTAS;

    const unsigned raw32 = smem_u32(dsm);
    const unsigned abase = (raw32 + 8191u) & ~8191u;   // 8KB-aligned LUT base
    char* ab = dsm + (abase - raw32);

    // ---- build LUT: 13 positions x 32 entries x 32 lanes x float2 ----
    // combined mask bit n: n<32 -> neuron 2n (pm0), n>=32 -> neuron 2(n-32)+1 (pm1)
    for (int p = 0; p < 13; p++) {
        char* bpp = ab + p * 8192 + lane * 8;
        *(float2*)bpp = make_float2(0.f, 0.f);
#pragma unroll
        for (int i = 0; i < 5; i++) {
            int n = 5 * p + i;
            float2 c = make_float2(0.f, 0.f);
            if (n < 64) {
                int j = (n < 32) ? 2 * n : 2 * (n - 32) + 1;
                c.x = V[(size_t)(2 * lane) * H_DIM + j];
                c.y = V[(size_t)(2 * lane + 1) * H_DIM + j];
            }
            *(float2*)(bpp + (1u << i) * 256) = c;
        }
        for (int v = 3; v < 32; v++) {
            if ((v & (v - 1)) == 0) continue;
            float2 e1 = *(const float2*)(bpp + (v & (v - 1)) * 256);
            float2 e2 = *(const float2*)(bpp + (v & (-v)) * 256);
            *(float2*)(bpp + v * 256) = make_float2(e1.x + e2.x, e1.y + e2.y);
        }
    }
    __syncwarp();

    unsigned bp[13];
#pragma unroll
    for (int p = 0; p < 13; p++) bp[p] = abase + p * 8192 + lane * 8;

    const float omb_h = 1.f - b_h;
    const ull a_h2 = pack2(a_h, a_h);
    const ull omb2 = pack2(omb_h, omb_h);
    const ull b_h2 = pack2(b_h, b_h);

    ull syn2 = 0ull, mem2 = 0ull;

    // wait for chunk 0, then init the prefetch ring
    while (acquire_ld(&g_done[0]) < PRE_CTAS) {}

    const int strideP = BATCH * H_DIM;
    const float* p = g_P + (size_t)b * H_DIM + 2 * lane;
    float2 cur[8];
#pragma unroll
    for (int q = 0; q < 8; q++) cur[q] = *(const float2*)(p + (size_t)q * strideP);
    const float* pf = p + (size_t)8 * strideP;

    ull* mptr = g_M + b;
    unsigned pm0 = 0u, pm1 = 0u;
    const unsigned M5 = 0x1F00u;
    const unsigned is0 = (lane == 0) ? 1u : 0u;

    for (int tb = 0; tb < T_STEPS; tb += 8) {
        if ((tb & (TCH - 1)) == 0) {
            const int cw = tb / TCH + 1;
            const int need = (cw < NTCH) ? cw : (NTCH - 1);
            while (acquire_ld(&g_done[need]) < PRE_CTAS) {}
        }
#pragma unroll
        for (int q8 = 0; q8 < 8; q8++) {
            // 13 lookups: 5-bit fields of (pm1:pm0) at addr bits 8..12
            ull h0 = lds_u64(((pm0 << 8)  & M5) | bp[0]);
            ull h1 = lds_u64(((pm0 << 3)  & M5) | bp[1]);
            ull h2 = lds_u64(((pm0 >> 2)  & M5) | bp[2]);
            ull h3 = lds_u64(((pm0 >> 7)  & M5) | bp[3]);
            ull h4 = lds_u64(((pm0 >> 12) & M5) | bp[4]);
            ull h5 = lds_u64(((pm0 >> 17) & M5) | bp[5]);
            ull h6 = lds_u64((__funnelshift_r(pm0, pm1, 22) & M5) | bp[6]);
            ull h7 = lds_u64(((pm1 << 5)  & M5) | bp[7]);
            ull h8 = lds_u64((pm1         & M5) | bp[8]);
            ull h9 = lds_u64(((pm1 >> 5)  & M5) | bp[9]);
            ull hA = lds_u64(((pm1 >> 10) & M5) | bp[10]);
            ull hB = lds_u64(((pm1 >> 15) & M5) | bp[11]);
            ull hC = lds_u64(((pm1 >> 20) & M5) | bp[12]);

            float2 c = cur[q8];
            cur[q8] = *(const float2*)pf;   // unconditional (g_P padded)
            pf += strideP;

            ull s0 = add2(h0, h1);
            ull s1 = add2(h2, h3);
            ull s2 = add2(h4, h5);
            ull s3 = add2(h6, h7);
            ull s4 = add2(h8, h9);
            ull s5 = add2(hA, hB);
            ull s6 = add2(hC, pack2(c.x, c.y));
            ull t0 = add2(s0, s1);
            ull t1 = add2(s2, s3);
            ull t2 = add2(s4, s5);
            ull tot = add2(add2(t0, t1), add2(t2, s6));

            syn2 = fma2g(a_h2, syn2, tot);
            mem2 = fma2g(b_h2, mem2, mul2(omb2, syn2));
            float m0 = lo32(mem2), m1 = hi32(mem2);
            bool sp0 = (m0 > 1.f);
            bool sp1 = (m1 > 1.f);
            m0 = sp0 ? 0.f : m0;
            m1 = sp1 ? 0.f : m1;
            mem2 = pack2(m0, m1);
            pm0 = __ballot_sync(0xffffffffu, sp0);
            pm1 = __ballot_sync(0xffffffffu, sp1);

            stg_pred(is0, mptr, (ull)pm0 | ((ull)pm1 << 32));
            mptr += BATCH;
        }
    }
}

// ============================================================
// Kernel 3: per-chunk local readout scans (CHUNK=32, 128 CTAs).
// ============================================================
__global__ __launch_bounds__(128) void readout_chunks(const float* __restrict__ Wo,
                                                      float* __restrict__ out,
                                                      float a_o, float b_o) {
    __shared__ float2 lutOb[8 * 256];

    const int tid = threadIdx.x;
    const int c   = blockIdx.x;

    for (int idx = tid; idx < 8 * 256; idx += 128) {
        int pp = idx >> 8, v = idx & 255;
        float2 s = make_float2(0.f, 0.f);
#pragma unroll
        for (int i = 0; i < 8; i++) {
            if (v & (1 << i)) {
                int j = (pp < 4) ? 2 * (8 * pp + i) : 2 * (8 * (pp - 4) + i) + 1;
                s.x += Wo[j];
                s.y += Wo[H_DIM + j];
            }
        }
        lutOb[idx] = s;
    }
    __syncthreads();

    const int b = tid;
    const ull a_o2  = pack2(a_o, a_o);
    const ull b_o2  = pack2(b_o, b_o);
    const ull ombo2 = pack2(1.f - b_o, 1.f - b_o);

    ull syno2 = 0ull, memo2 = 0ull;

    const ull* mp = g_M + ((long long)c * CHUNK - 1) * BATCH + b;
    ull ring[8];
#pragma unroll
    for (int q = 0; q < 8; q++)
        ring[q] = (c == 0 && q == 0) ? 0ull : mp[(size_t)q * BATCH];
    const ull* pfm = mp + (size_t)8 * BATCH;

    ull* optr = (ull*)out + (size_t)c * CHUNK * BATCH + b;

    for (int jb = 0; jb < CHUNK; jb += 8) {
#pragma unroll
        for (int q8 = 0; q8 < 8; q8++) {
            const int j = jb + q8;
            ull m = ring[q8];
            ring[q8] = *pfm;   // unconditional (g_M padded)
            pfm += BATCH;

            unsigned p0 = (unsigned)m, p1 = (unsigned)(m >> 32);
            ull r0 = add2(*(const ull*)&lutOb[0 * 256 + (p0 & 255u)],
                          *(const ull*)&lutOb[4 * 256 + (p1 & 255u)]);
            ull r1 = add2(*(const ull*)&lutOb[1 * 256 + ((p0 >> 8) & 255u)],
                          *(const ull*)&lutOb[5 * 256 + ((p1 >> 8) & 255u)]);
            ull r2 = add2(*(const ull*)&lutOb[2 * 256 + ((p0 >> 16) & 255u)],
                          *(const ull*)&lutOb[6 * 256 + ((p1 >> 16) & 255u)]);
            ull r3 = add2(*(const ull*)&lutOb[3 * 256 + (p0 >> 24)],
                          *(const ull*)&lutOb[7 * 256 + (p1 >> 24)]);
            ull d2 = add2(add2(r0, r1), add2(r2, r3));

            syno2 = fma2g(a_o2, syno2, d2);
            memo2 = fma2g(b_o2, memo2, mul2(ombo2, syno2));
            optr[(size_t)j * BATCH] = memo2;
        }
    }
    g_S[c * BATCH + b] = make_ulonglong2(syno2, memo2);
}

// ============================================================
// Kernel 4: chunk prefix (NCHUNK=128, 16-deep block prefetch).
// ============================================================
__global__ __launch_bounds__(128) void readout_prefix(float a_o, float b_o) {
    const int b = threadIdx.x;

    float ap = a_o, bpw = b_o, g = (1.f - b_o) * a_o;
    float aC = 0.f, bC = 0.f, gC = 0.f;
    for (int j = 0; j < CHUNK; j++) {
        if (b == 0) g_tab[j] = make_float2(bpw, g);
        if (j == CHUNK - 1) { aC = ap; bC = bpw; gC = g; }
        ap *= a_o;
        bpw *= b_o;
        g = b_o * g + (1.f - b_o) * ap;
    }

    const ull aC2 = pack2(aC, aC);
    const ull bC2 = pack2(bC, bC);
    const ull gC2 = pack2(gC, gC);

    ulonglong2 buf[2][16];
#pragma unroll
    for (int q = 0; q < 16; q++) buf[0][q] = g_S[q * BATCH + b];

    ull S = 0ull, M = 0ull;
#pragma unroll
    for (int blk = 0; blk < NCHUNK / 16; blk++) {
        if (blk < NCHUNK / 16 - 1) {
#pragma unroll
            for (int q = 0; q < 16; q++)
                buf[(blk + 1) & 1][q] = g_S[((blk + 1) * 16 + q) * BATCH + b];
        }
#pragma unroll
        for (int q = 0; q < 16; q++) {
            int c = blk * 16 + q;
            g_Pref[c * BATCH + b] = make_ulonglong2(S, M);
            ulonglong2 sm = buf[blk & 1][q];
            ull Sold = S;
            S = fma2g(aC2, S, sm.x);
            M = add2(fma2g(bC2, M, sm.y), mul2(gC2, Sold));
        }
    }
}

// ============================================================
// Kernel 5: fixup: out[t][b] += b^{j+1}*M_c + g_j*S_c
// ============================================================
__global__ __launch_bounds__(256) void readout_fix(float* __restrict__ out) {
    const size_t idx = (size_t)blockIdx.x * 256 + threadIdx.x;
    const int t = (int)(idx >> 7);
    const int b = (int)(idx & 127);
    const int c = t / CHUNK;
    const int j = t % CHUNK;

    float2 tab = g_tab[j];
    ulonglong2 pref = g_Pref[c * BATCH + b];
    ull fix = add2(mul2(pack2(tab.x, tab.x), pref.y),
                   mul2(pack2(tab.y, tab.y), pref.x));
    ull* o = (ull*)out + idx;
    *o = add2(*o, fix);
}

// ============================================================
extern "C" void kernel_launch(void* const* d_in, const int* in_sizes, int n_in,
                              void* d_out, int out_size) {
    const float* x  = (const float*)d_in[0];
    const float* Wh = (const float*)d_in[1];
    const float* V  = (const float*)d_in[2];
    const float* Wo = (const float*)d_in[3];
    float* out = (float*)d_out;

    const double S = log1p(exp(1.0));
    const float a_h = expf((float)(-0.004 / (S * 0.01)));
    const float b_h = expf((float)(-0.004 / (S * 0.02)));

    const int smem_fused = 13 * 8192 + 8192;   // 112 KB (LUT + align pad; aliased xp/wp)
    cudaFuncSetAttribute(fused_kernel, cudaFuncAttributeMaxDynamicSharedMemorySize,
                         smem_fused);
    cudaFuncSetAttribute(fused_kernel, cudaFuncAttributePreferredSharedMemoryCarveout,
                         100);

    zero_done<<<1, 64>>>();
    fused_kernel<<<PRE_CTAS + SCAN_CTAS, 128, smem_fused>>>(x, Wh, V, a_h, b_h);
    readout_chunks<<<NCHUNK, 128>>>(Wo, out, a_h, b_h);
    readout_prefix<<<1, 128>>>(a_h, b_h);
    readout_fix<<<(T_STEPS * BATCH) / 256, 256>>>(out);
}

// round 16
// speedup vs baseline: 2.1866x; 1.1512x over previous
#include <cuda_runtime.h>
#include <math.h>

#define T_STEPS 4096
#define BATCH   128
#define IN_DIM  96
#define H_DIM   64
#define OUT_DIM 2

#define CHUNK   32
#define NCHUNK  (T_STEPS / CHUNK)   // 128 (readout chunking)

#define TCH     64                  // producer/scan sync chunk (timesteps)
#define NTCH    (T_STEPS / TCH)     // 64
#define NCTA    128

typedef unsigned long long ull;

// Scratch (padded by 8 timesteps so prefetches need no bounds branch)
__device__ float g_P[(size_t)(T_STEPS + 8) * BATCH * H_DIM];
__device__ ull   g_M[(size_t)(T_STEPS + 8) * BATCH];
__device__ ulonglong2 g_S[NCHUNK * BATCH];
__device__ ulonglong2 g_Pref[NCHUNK * BATCH];
__device__ float2 g_tab[CHUNK];
__device__ int    g_done[NTCH];      // producer progress (counts to NCTA)
__device__ int    g_scandone[NTCH];  // scan progress (counts to NCTA)

// ---------- packed f32x2 helpers ----------
__device__ __forceinline__ void fma2(ull& d, ull a, ull b) {
    asm("fma.rn.f32x2 %0, %1, %2, %0;" : "+l"(d) : "l"(a), "l"(b));
}
__device__ __forceinline__ ull fma2g(ull a, ull b, ull c) {
    ull d;
    asm("fma.rn.f32x2 %0, %1, %2, %3;" : "=l"(d) : "l"(a), "l"(b), "l"(c));
    return d;
}
__device__ __forceinline__ ull add2(ull a, ull b) {
    ull d;
    asm("add.rn.f32x2 %0, %1, %2;" : "=l"(d) : "l"(a), "l"(b));
    return d;
}
__device__ __forceinline__ ull mul2(ull a, ull b) {
    ull d;
    asm("mul.rn.f32x2 %0, %1, %2;" : "=l"(d) : "l"(a), "l"(b));
    return d;
}
__device__ __forceinline__ ull pack2(float x, float y) {
    ull r;
    asm("mov.b64 %0, {%1, %2};" : "=l"(r) : "f"(x), "f"(y));
    return r;
}
__device__ __forceinline__ float lo32(ull v) { return __uint_as_float((unsigned)v); }
__device__ __forceinline__ float hi32(ull v) { return __uint_as_float((unsigned)(v >> 32)); }

__device__ __forceinline__ unsigned smem_u32(const void* p) {
    unsigned a;
    asm("{ .reg .u64 t; cvta.to.shared.u64 t, %1; cvt.u32.u64 %0, t; }" : "=r"(a) : "l"(p));
    return a;
}
__device__ __forceinline__ ull lds_u64(unsigned a) {
    ull v;
    asm("ld.shared.b64 %0, [%1];" : "=l"(v) : "r"(a));
    return v;
}
// predicated store WITHOUT a compiler memory barrier (nothing in-kernel
// reads g_M on this path; ordering vs the release red is volatile-volatile)
__device__ __forceinline__ void stg_pred(unsigned cond, ull* addr, ull v) {
    asm volatile(
        "{\n\t.reg .pred p;\n\tsetp.ne.u32 p, %0, 0;\n\t@p st.global.b64 [%1], %2;\n\t}"
        :: "r"(cond), "l"(addr), "l"(v));
}
__device__ __forceinline__ void release_inc(int* p) {
    asm volatile("red.release.gpu.global.add.s32 [%0], 1;" :: "l"(p) : "memory");
}
__device__ __forceinline__ int acquire_ld(const int* p) {
    int v;
    asm volatile("ld.acquire.gpu.global.s32 %0, [%1];" : "=r"(v) : "l"(p) : "memory");
    return v;
}

// ============================================================
// Kernel 0: reset progress counters (graph-replay safe)
// ============================================================
__global__ void zero_done() {
    if (threadIdx.x < NTCH)       g_done[threadIdx.x] = 0;
    else if (threadIdx.x < 2 * NTCH) g_scandone[threadIdx.x - NTCH] = 0;
}

// ============================================================
// HYBRID kernel: 128 CTAs x 128 threads, ONE CTA PER SM.
//  warps 0,1 (SMSP0/1): input-GEMM producer for all 64 chunks,
//    then readout chunk `bid` once the scan fleet has published
//    the covering masks.
//  warp 3   (SMSP3)   : serial scan for batch b = bid
//    (13x 5-bit-group LUT recurrent dot), publishing progress
//    per 64-step chunk.
//  warp 2: idle.
// Static smem: xp/wp tiles (48KB) + readout byte-LUT (16KB).
// Dynamic smem: 104KB scan LUT + 8KB alignment pad.
// ============================================================
__global__ __launch_bounds__(128, 1) void hybrid_kernel(const float* __restrict__ x,
                                                        const float* __restrict__ Wh,
                                                        const float* __restrict__ V,
                                                        const float* __restrict__ Wo,
                                                        float* __restrict__ out,
                                                        float a_h, float b_h) {
    extern __shared__ __align__(16) char dsm[];   // scan LUT region
    __shared__ ull xp[48][64];                    // 24 KB producer x tile
    __shared__ ull wp[48][64];                    // 24 KB producer W tile
    __shared__ float2 lutOb[8 * 256];             // 16 KB readout byte-LUT

    const int tid  = threadIdx.x;
    const int bid  = blockIdx.x;

    if (tid < 64) {
        // ================= PRODUCER (warps 0,1) =================
        const int fr = tid >> 3;
        const int fq = tid & 7;

        // readout byte-LUT (built once; used after production)
        for (int idx = tid; idx < 8 * 256; idx += 64) {
            int pp = idx >> 8, v = idx & 255;
            float2 s = make_float2(0.f, 0.f);
#pragma unroll
            for (int i = 0; i < 8; i++) {
                if (v & (1 << i)) {
                    int j = (pp < 4) ? 2 * (8 * pp + i) : 2 * (8 * (pp - 4) + i) + 1;
                    s.x += Wo[j];
                    s.y += Wo[H_DIM + j];
                }
            }
            lutOb[idx] = s;
        }

        // ---- W tile fill (once) ----
#pragma unroll
        for (int rr = 0; rr < 8; rr++) {
            int c = rr * 8 + fr;
            const float4* src = (const float4*)(Wh + (size_t)c * IN_DIM) + fq * 3;
#pragma unroll
            for (int j = 0; j < 3; j++) {
                float4 f = src[j];
                int kk = (fq * 3 + j) * 2;
                *(float2*)&wp[kk][c]     = make_float2(f.x, f.y);
                *(float2*)&wp[kk + 1][c] = make_float2(f.z, f.w);
            }
        }

        const int r0 = (tid & 7) * 8;
        const int c0 = (tid >> 3) * 8;

        for (int c = 0; c < NTCH; c++) {
            const long long row0 = ((long long)c * NCTA + bid) * 64;

            // ---- x fill (shifted one step; t==0 rows zero) ----
#pragma unroll
            for (int rr = 0; rr < 8; rr++) {
                int r = rr * 8 + fr;
                long long g = row0 + r;
#pragma unroll
                for (int j = 0; j < 3; j++) {
                    float4 f = make_float4(0.f, 0.f, 0.f, 0.f);
                    if (g >= BATCH)
                        f = ((const float4*)(x + (g - BATCH) * IN_DIM))[fq * 3 + j];
                    int kk = (fq * 3 + j) * 2;
                    *(float2*)&xp[kk][r]     = make_float2(f.x, f.y);
                    *(float2*)&xp[kk + 1][r] = make_float2(f.z, f.w);
                }
            }
            asm volatile("bar.sync 1, 64;" ::: "memory");

            ull acc[8][8];
#pragma unroll
            for (int i = 0; i < 8; i++)
#pragma unroll
                for (int j = 0; j < 8; j++) acc[i][j] = 0ull;

#pragma unroll 2
            for (int kk = 0; kk < 48; kk++) {
                ulonglong2 A[4], B[4];
#pragma unroll
                for (int j = 0; j < 4; j++) {
                    A[j] = *(const ulonglong2*)&xp[kk][r0 + 2 * j];
                    B[j] = *(const ulonglong2*)&wp[kk][c0 + 2 * j];
                }
#pragma unroll
                for (int ri = 0; ri < 8; ri++) {
                    ull av = (ri & 1) ? A[ri >> 1].y : A[ri >> 1].x;
#pragma unroll
                    for (int cj = 0; cj < 4; cj++) {
                        fma2(acc[ri][2 * cj],     av, B[cj].x);
                        fma2(acc[ri][2 * cj + 1], av, B[cj].y);
                    }
                }
            }

#pragma unroll
            for (int ri = 0; ri < 8; ri++) {
                float4 o0, o1;
                o0.x = lo32(acc[ri][0]) + hi32(acc[ri][0]);
                o0.y = lo32(acc[ri][1]) + hi32(acc[ri][1]);
                o0.z = lo32(acc[ri][2]) + hi32(acc[ri][2]);
                o0.w = lo32(acc[ri][3]) + hi32(acc[ri][3]);
                o1.x = lo32(acc[ri][4]) + hi32(acc[ri][4]);
                o1.y = lo32(acc[ri][5]) + hi32(acc[ri][5]);
                o1.z = lo32(acc[ri][6]) + hi32(acc[ri][6]);
                o1.w = lo32(acc[ri][7]) + hi32(acc[ri][7]);
                float* dst = g_P + (size_t)(row0 + r0 + ri) * H_DIM + c0;
                *(float4*)dst       = o0;
                *(float4*)(dst + 4) = o1;
            }

            __threadfence();   // publish g_P at gpu scope
            asm volatile("bar.sync 1, 64;" ::: "memory");
            if (tid == 0) release_inc(&g_done[c]);
        }

        // ================= READOUT (chunk = bid) =================
        {
            const int cc = bid;
            const int need64 = (cc * CHUNK + CHUNK - 1) >> 6;
            if (tid == 0)
                while (acquire_ld(&g_scandone[need64]) < NCTA) {}
            asm volatile("bar.sync 1, 64;" ::: "memory");

            const ull a_o2  = pack2(a_h, a_h);
            const ull b_o2  = pack2(b_h, b_h);
            const ull ombo2 = pack2(1.f - b_h, 1.f - b_h);

#pragma unroll
            for (int half = 0; half < 2; half++) {
                const int b = tid + half * 64;

                ull syno2 = 0ull, memo2 = 0ull;
                const ull* mp = g_M + ((long long)cc * CHUNK - 1) * BATCH + b;
                ull ring[8];
#pragma unroll
                for (int q = 0; q < 8; q++)
                    ring[q] = (cc == 0 && q == 0) ? 0ull : mp[(size_t)q * BATCH];
                const ull* pfm = mp + (size_t)8 * BATCH;

                ull* optr = (ull*)out + (size_t)cc * CHUNK * BATCH + b;

                for (int jb = 0; jb < CHUNK; jb += 8) {
#pragma unroll
                    for (int q8 = 0; q8 < 8; q8++) {
                        const int j = jb + q8;
                        ull m = ring[q8];
                        ring[q8] = *pfm;   // unconditional (g_M padded)
                        pfm += BATCH;

                        unsigned p0 = (unsigned)m, p1 = (unsigned)(m >> 32);
                        ull r0_ = add2(*(const ull*)&lutOb[0 * 256 + (p0 & 255u)],
                                       *(const ull*)&lutOb[4 * 256 + (p1 & 255u)]);
                        ull r1_ = add2(*(const ull*)&lutOb[1 * 256 + ((p0 >> 8) & 255u)],
                                       *(const ull*)&lutOb[5 * 256 + ((p1 >> 8) & 255u)]);
                        ull r2_ = add2(*(const ull*)&lutOb[2 * 256 + ((p0 >> 16) & 255u)],
                                       *(const ull*)&lutOb[6 * 256 + ((p1 >> 16) & 255u)]);
                        ull r3_ = add2(*(const ull*)&lutOb[3 * 256 + (p0 >> 24)],
                                       *(const ull*)&lutOb[7 * 256 + (p1 >> 24)]);
                        ull d2 = add2(add2(r0_, r1_), add2(r2_, r3_));

                        syno2 = fma2g(a_o2, syno2, d2);
                        memo2 = fma2g(b_o2, memo2, mul2(ombo2, syno2));
                        optr[(size_t)j * BATCH] = memo2;
                    }
                }
                g_S[cc * BATCH + b] = make_ulonglong2(syno2, memo2);
            }
        }
        return;
    }

    // ================= SCAN (warp 3, SMSP3) =================
    if (tid < 96) return;
    const int lane = tid - 96;
    const int b    = bid;

    const unsigned raw32 = smem_u32(dsm);
    const unsigned abase = (raw32 + 8191u) & ~8191u;   // 8KB-aligned LUT base
    char* ab = dsm + (abase - raw32);

    // ---- build LUT: 13 positions x 32 entries x 32 lanes x float2 ----
    for (int p = 0; p < 13; p++) {
        char* bpp = ab + p * 8192 + lane * 8;
        *(float2*)bpp = make_float2(0.f, 0.f);
#pragma unroll
        for (int i = 0; i < 5; i++) {
            int n = 5 * p + i;
            float2 c = make_float2(0.f, 0.f);
            if (n < 64) {
                int j = (n < 32) ? 2 * n : 2 * (n - 32) + 1;
                c.x = V[(size_t)(2 * lane) * H_DIM + j];
                c.y = V[(size_t)(2 * lane + 1) * H_DIM + j];
            }
            *(float2*)(bpp + (1u << i) * 256) = c;
        }
        for (int v = 3; v < 32; v++) {
            if ((v & (v - 1)) == 0) continue;
            float2 e1 = *(const float2*)(bpp + (v & (v - 1)) * 256);
            float2 e2 = *(const float2*)(bpp + (v & (-v)) * 256);
            *(float2*)(bpp + v * 256) = make_float2(e1.x + e2.x, e1.y + e2.y);
        }
    }
    __syncwarp();

    unsigned bp[13];
#pragma unroll
    for (int p = 0; p < 13; p++) bp[p] = abase + p * 8192 + lane * 8;

    const float omb_h = 1.f - b_h;
    const ull a_h2 = pack2(a_h, a_h);
    const ull omb2 = pack2(omb_h, omb_h);
    const ull b_h2 = pack2(b_h, b_h);

    ull syn2 = 0ull, mem2 = 0ull;

    while (acquire_ld(&g_done[0]) < NCTA) {}

    const int strideP = BATCH * H_DIM;
    const float* p = g_P + (size_t)b * H_DIM + 2 * lane;
    float2 cur[8];
#pragma unroll
    for (int q = 0; q < 8; q++) cur[q] = *(const float2*)(p + (size_t)q * strideP);
    const float* pf = p + (size_t)8 * strideP;

    ull* mptr = g_M + b;
    unsigned pm0 = 0u, pm1 = 0u;
    const unsigned M5 = 0x1F00u;
    const unsigned is0 = (lane == 0) ? 1u : 0u;

    for (int tb = 0; tb < T_STEPS; tb += 8) {
        if ((tb & (TCH - 1)) == 0) {
            const int cw = tb / TCH;
            const int need = (cw + 1 < NTCH) ? cw + 1 : NTCH - 1;
            while (acquire_ld(&g_done[need]) < NCTA) {}
            if (is0 && cw > 0) release_inc(&g_scandone[cw - 1]);
        }
#pragma unroll
        for (int q8 = 0; q8 < 8; q8++) {
            ull h0 = lds_u64(((pm0 << 8)  & M5) | bp[0]);
            ull h1 = lds_u64(((pm0 << 3)  & M5) | bp[1]);
            ull h2 = lds_u64(((pm0 >> 2)  & M5) | bp[2]);
            ull h3 = lds_u64(((pm0 >> 7)  & M5) | bp[3]);
            ull h4 = lds_u64(((pm0 >> 12) & M5) | bp[4]);
            ull h5 = lds_u64(((pm0 >> 17) & M5) | bp[5]);
            ull h6 = lds_u64((__funnelshift_r(pm0, pm1, 22) & M5) | bp[6]);
            ull h7 = lds_u64(((pm1 << 5)  & M5) | bp[7]);
            ull h8 = lds_u64((pm1         & M5) | bp[8]);
            ull h9 = lds_u64(((pm1 >> 5)  & M5) | bp[9]);
            ull hA = lds_u64(((pm1 >> 10) & M5) | bp[10]);
            ull hB = lds_u64(((pm1 >> 15) & M5) | bp[11]);
            ull hC = lds_u64(((pm1 >> 20) & M5) | bp[12]);

            float2 c = cur[q8];
            cur[q8] = *(const float2*)pf;   // unconditional (g_P padded)
            pf += strideP;

            ull s0 = add2(h0, h1);
            ull s1 = add2(h2, h3);
            ull s2 = add2(h4, h5);
            ull s3 = add2(h6, h7);
            ull s4 = add2(h8, h9);
            ull s5 = add2(hA, hB);
            ull s6 = add2(hC, pack2(c.x, c.y));
            ull t0 = add2(s0, s1);
            ull t1 = add2(s2, s3);
            ull t2 = add2(s4, s5);
            ull tot = add2(add2(t0, t1), add2(t2, s6));

            syn2 = fma2g(a_h2, syn2, tot);
            mem2 = fma2g(b_h2, mem2, mul2(omb2, syn2));
            float m0 = lo32(mem2), m1 = hi32(mem2);
            bool sp0 = (m0 > 1.f);
            bool sp1 = (m1 > 1.f);
            m0 = sp0 ? 0.f : m0;
            m1 = sp1 ? 0.f : m1;
            mem2 = pack2(m0, m1);
            pm0 = __ballot_sync(0xffffffffu, sp0);
            pm1 = __ballot_sync(0xffffffffu, sp1);

            stg_pred(is0, mptr, (ull)pm0 | ((ull)pm1 << 32));
            mptr += BATCH;
        }
    }
    if (is0) release_inc(&g_scandone[NTCH - 1]);
}

// ============================================================
// Kernel 4: chunk prefix (NCHUNK=128, 16-deep block prefetch).
// ============================================================
__global__ __launch_bounds__(128) void readout_prefix(float a_o, float b_o) {
    const int b = threadIdx.x;

    float ap = a_o, bpw = b_o, g = (1.f - b_o) * a_o;
    float aC = 0.f, bC = 0.f, gC = 0.f;
    for (int j = 0; j < CHUNK; j++) {
        if (b == 0) g_tab[j] = make_float2(bpw, g);
        if (j == CHUNK - 1) { aC = ap; bC = bpw; gC = g; }
        ap *= a_o;
        bpw *= b_o;
        g = b_o * g + (1.f - b_o) * ap;
    }

    const ull aC2 = pack2(aC, aC);
    const ull bC2 = pack2(bC, bC);
    const ull gC2 = pack2(gC, gC);

    ulonglong2 buf[2][16];
#pragma unroll
    for (int q = 0; q < 16; q++) buf[0][q] = g_S[q * BATCH + b];

    ull S = 0ull, M = 0ull;
#pragma unroll
    for (int blk = 0; blk < NCHUNK / 16; blk++) {
        if (blk < NCHUNK / 16 - 1) {
#pragma unroll
            for (int q = 0; q < 16; q++)
                buf[(blk + 1) & 1][q] = g_S[((blk + 1) * 16 + q) * BATCH + b];
        }
#pragma unroll
        for (int q = 0; q < 16; q++) {
            int c = blk * 16 + q;
            g_Pref[c * BATCH + b] = make_ulonglong2(S, M);
            ulonglong2 sm = buf[blk & 1][q];
            ull Sold = S;
            S = fma2g(aC2, S, sm.x);
            M = add2(fma2g(bC2, M, sm.y), mul2(gC2, Sold));
        }
    }
}

// ============================================================
// Kernel 5: fixup: out[t][b] += b^{j+1}*M_c + g_j*S_c
// ============================================================
__global__ __launch_bounds__(256) void readout_fix(float* __restrict__ out) {
    const size_t idx = (size_t)blockIdx.x * 256 + threadIdx.x;
    const int t = (int)(idx >> 7);
    const int b = (int)(idx & 127);
    const int c = t / CHUNK;
    const int j = t % CHUNK;

    float2 tab = g_tab[j];
    ulonglong2 pref = g_Pref[c * BATCH + b];
    ull fix = add2(mul2(pack2(tab.x, tab.x), pref.y),
                   mul2(pack2(tab.y, tab.y), pref.x));
    ull* o = (ull*)out + idx;
    *o = add2(*o, fix);
}

// ============================================================
extern "C" void kernel_launch(void* const* d_in, const int* in_sizes, int n_in,
                              void* d_out, int out_size) {
    const float* x  = (const float*)d_in[0];
    const float* Wh = (const float*)d_in[1];
    const float* V  = (const float*)d_in[2];
    const float* Wo = (const float*)d_in[3];
    float* out = (float*)d_out;

    const double S = log1p(exp(1.0));
    const float a_h = expf((float)(-0.004 / (S * 0.01)));
    const float b_h = expf((float)(-0.004 / (S * 0.02)));

    const int smem_dyn = 13 * 8192 + 8192;   // 112 KB dynamic (scan LUT + align pad)
    cudaFuncSetAttribute(hybrid_kernel, cudaFuncAttributeMaxDynamicSharedMemorySize,
                         smem_dyn);
    cudaFuncSetAttribute(hybrid_kernel, cudaFuncAttributePreferredSharedMemoryCarveout,
                         100);

    zero_done<<<1, 128>>>();
    hybrid_kernel<<<NCTA, 128, smem_dyn>>>(x, Wh, V, Wo, out, a_h, b_h);
    readout_prefix<<<1, 128>>>(a_h, b_h);
    readout_fix<<<(T_STEPS * BATCH) / 256, 256>>>(out);
}